// round 15
// baseline (speedup 1.0000x reference)
#include <cuda_runtime.h>
#include <cuda_bf16.h>
#include <cuda_fp16.h>
#include <cstdint>
#include <math.h>

#define BB 2
#define SS 2048
#define DIMV 1024
#define NH 16
#define FFV 4096
#define MTOT (BB*SS)          /* 4096 rows */
#define KP1 DIMV              /* 1024: plain fp16, K = 1024 */
#define KP2 FFV               /* 4096: plain fp16, K = 4096 */

// ---------------- scratch (device globals: allocation-free) ----------------
__device__ float g_tmp[MTOT * DIMV];
__device__ float g_x1 [MTOT * DIMV];

__device__ __align__(16) __half g_qs[(size_t)BB * NH * SS * 64];
__device__ __align__(16) __half g_ks[(size_t)BB * NH * SS * 64];
__device__ __align__(16) __half g_v [(size_t)BB * NH * SS * 64];

__device__ __align__(16) __half g_xb  [MTOT * KP1];
__device__ __align__(16) __half g_ctxb[MTOT * KP1];
__device__ __align__(16) __half g_x1b [MTOT * KP1];
__device__ __align__(16) __half g_hb  [(size_t)MTOT * KP2];
__device__ __align__(16) __half g_wqkv[3 * DIMV * KP1];
__device__ __align__(16) __half g_wao [DIMV * KP1];
__device__ __align__(16) __half g_wgl [(size_t)2 * FFV * KP1];  // interleaved gate/lin
__device__ __align__(16) __half g_wfo [DIMV * KP2];

// ---------------- PTX helpers ----------------------------------------------
__device__ __forceinline__ uint32_t smem_u32(const void* p) {
    uint32_t a;
    asm("{ .reg .u64 t; cvta.to.shared.u64 t, %1; cvt.u32.u64 %0, t; }"
        : "=r"(a) : "l"(p));
    return a;
}
__device__ __forceinline__ void cpa16(uint32_t dst, const void* src) {
    asm volatile("cp.async.cg.shared.global [%0], [%1], 16;" :: "r"(dst), "l"(src));
}
#define CP_COMMIT() asm volatile("cp.async.commit_group;" ::: "memory")

#define LDSM4(r, addr) \
    asm volatile("ldmatrix.sync.aligned.m8n8.x4.shared.b16 {%0,%1,%2,%3}, [%4];" \
        : "=r"((r)[0]), "=r"((r)[1]), "=r"((r)[2]), "=r"((r)[3]) : "r"(addr))

#define LDSM4T(r, addr) \
    asm volatile("ldmatrix.sync.aligned.m8n8.x4.trans.shared.b16 {%0,%1,%2,%3}, [%4];" \
        : "=r"((r)[0]), "=r"((r)[1]), "=r"((r)[2]), "=r"((r)[3]) : "r"(addr))

#define MMAF16(d, a, b0, b1) \
    asm volatile("mma.sync.aligned.m16n8k16.row.col.f32.f16.f16.f32 " \
        "{%0,%1,%2,%3},{%4,%5,%6,%7},{%8,%9},{%0,%1,%2,%3};" \
        : "+f"((d)[0]), "+f"((d)[1]), "+f"((d)[2]), "+f"((d)[3]) \
        : "r"((a)[0]), "r"((a)[1]), "r"((a)[2]), "r"((a)[3]), "r"(b0), "r"(b1))

__device__ __forceinline__ uint32_t pkf16(float lo, float hi) {
    uint32_t r;
    asm("cvt.rn.f16x2.f32 %0, %1, %2;" : "=r"(r) : "f"(hi), "f"(lo));
    return r;
}
__device__ __forceinline__ uint2 pack4(float4 v) {
    uint2 u;
    u.x = pkf16(v.x, v.y);
    u.y = pkf16(v.z, v.w);
    return u;
}

// ---------------- fp16 HMMA GEMM: C[M,N] = A[M,Kp] @ W[N,Kp]^T --------------
// CTA 128x128, 8 warps (2x4), warp 64x32, BK=64, 3-stage cp.async pipeline.
// EPI=0: plain fp32 store.
// EPI=1: GLU epilogue -> fp16 HB over KP2.
// EPI=2: QKV epilogue: q/k RoPE (paired cols, fast trig) -> f16 head-major.
#define GSTAGES 3
#define GSTAGE_BYTES 32768          /* A 16KB + B 16KB */
#define GEMM_SMEM (GSTAGES * GSTAGE_BYTES)

template<int EPI>
__global__ void __launch_bounds__(256) gemm_mma_t(
    const __half* __restrict__ A, const __half* __restrict__ W,
    float* __restrict__ C, __half* __restrict__ HB,
    const float* __restrict__ gb, const float* __restrict__ lb,
    __half* __restrict__ Qd, __half* __restrict__ Kd, __half* __restrict__ Vd,
    int N, int Kp)
{
    extern __shared__ char sm[];
    const uint32_t smb = smem_u32(sm);
    const int tid  = threadIdx.x;
    const int wid  = tid >> 5, lane = tid & 31;
    const int wm   = (wid >> 2) << 6;
    const int wn   = (wid & 3) << 5;
    const int m0   = blockIdx.y << 7, n0 = blockIdx.x << 7;
    const int quad = lane >> 3, l8 = lane & 7;

    float acc[4][4][4];
#pragma unroll
    for (int i = 0; i < 4; ++i)
#pragma unroll
        for (int j = 0; j < 4; ++j)
#pragma unroll
            for (int v = 0; v < 4; ++v) acc[i][j][v] = 0.f;

    auto load_stage = [&](int kt) {
        const int s = kt % GSTAGES;
        const uint32_t sa = smb + s * GSTAGE_BYTES;
        const uint32_t sb = sa + 16384;
        const size_t kbase = (size_t)kt << 6;
#pragma unroll
        for (int p = 0; p < 4; ++p) {
            int chunk = (p << 8) + tid;
            int r = chunk >> 3, kc = chunk & 7;
            cpa16(sa + r * 128 + ((kc ^ (r & 7)) << 4),
                  (const char*)(A + (size_t)(m0 + r) * Kp + kbase + kc * 8));
        }
#pragma unroll
        for (int p = 0; p < 4; ++p) {
            int chunk = (p << 8) + tid;
            int r = chunk >> 3, kc = chunk & 7;
            cpa16(sb + r * 128 + ((kc ^ (r & 7)) << 4),
                  (const char*)(W + (size_t)(n0 + r) * Kp + kbase + kc * 8));
        }
        CP_COMMIT();
    };

    const int nk = Kp >> 6;
    load_stage(0);
    load_stage(1);

    for (int kt = 0; kt < nk; ++kt) {
        const int s = kt % GSTAGES;
        asm volatile("cp.async.wait_group 1;" ::: "memory");
        __syncthreads();
        if (kt + 2 < nk) load_stage(kt + 2); else CP_COMMIT();

        const uint32_t sa = smb + s * GSTAGE_BYTES;
        const uint32_t sb = sa + 16384;
#pragma unroll
        for (int ks = 0; ks < 4; ++ks) {
            const int k0c = ks << 1;
            uint32_t a[4][4], b[2][4];
#pragma unroll
            for (int mf = 0; mf < 4; ++mf) {
                int r  = wm + (mf << 4) + ((quad & 1) << 3) + l8;
                int kc = k0c + (quad >> 1);
                LDSM4(a[mf], sa + r * 128 + ((kc ^ (r & 7)) << 4));
            }
#pragma unroll
            for (int np = 0; np < 2; ++np) {
                int r  = wn + (np << 4) + ((quad >> 1) << 3) + l8;
                int kc = k0c + (quad & 1);
                LDSM4(b[np], sb + r * 128 + ((kc ^ (r & 7)) << 4));
            }
#pragma unroll
            for (int mf = 0; mf < 4; ++mf) {
#pragma unroll
                for (int np = 0; np < 2; ++np) {
                    MMAF16(acc[mf][2 * np],     a[mf], b[np][0], b[np][1]);
                    MMAF16(acc[mf][2 * np + 1], a[mf], b[np][2], b[np][3]);
                }
            }
        }
    }

    const int tr = lane >> 2, tc = (lane & 3) << 1;
    if (EPI == 0) {
#pragma unroll
        for (int mf = 0; mf < 4; ++mf) {
            int row = m0 + wm + (mf << 4) + tr;
            float* c0 = C + (size_t)row * N + n0 + wn;
            float* c1 = c0 + (size_t)8 * N;
#pragma unroll
            for (int nf = 0; nf < 4; ++nf) {
                *(float2*)(c0 + (nf << 3) + tc) = make_float2(acc[mf][nf][0], acc[mf][nf][1]);
                *(float2*)(c1 + (nf << 3) + tc) = make_float2(acc[mf][nf][2], acc[mf][nf][3]);
            }
        }
    } else if (EPI == 1) {
        // interleaved cols: even col = gate_c, odd col = lin_c, c = gcol>>1.
#pragma unroll
        for (int mf = 0; mf < 4; ++mf) {
            int row0 = m0 + wm + (mf << 4) + tr;
#pragma unroll
            for (int nf = 0; nf < 4; ++nf) {
                int c = (n0 + wn + (nf << 3) + tc) >> 1;
                float gbv = gb[c], lbv = lb[c];
                float h0 = (acc[mf][nf][1] + lbv) *
                           (1.f / (1.f + __expf(-(acc[mf][nf][0] + gbv))));
                float h1 = (acc[mf][nf][3] + lbv) *
                           (1.f / (1.f + __expf(-(acc[mf][nf][2] + gbv))));
                float h0p = __shfl_xor_sync(0xffffffffu, h0, 1);
                float h1p = __shfl_xor_sync(0xffffffffu, h1, 1);
                if ((lane & 1) == 0) {
                    __half2 hi0 = {__float2half_rn(h0), __float2half_rn(h0p)};
                    __half2 hi1 = {__float2half_rn(h1), __float2half_rn(h1p)};
                    __half* p0 = HB + (size_t)row0 * KP2 + c;
                    __half* p1 = p0 + (size_t)8 * KP2;
                    *(__half2*)(p0) = hi0;
                    *(__half2*)(p1) = hi1;
                }
            }
        }
    } else {
        // EPI == 2: QKV epilogue. Permuted weight rows -> thread holds RoPE
        // pair (x1_j, x2_j) in adjacent cols. q/k stored head-major f16.
        const float RC = 9.210340371976184f / 32.0f;
#pragma unroll
        for (int nf = 0; nf < 4; ++nf) {
            int col = n0 + wn + (nf << 3) + tc;   // even
            int sec = col >> 10;
            int cc  = col & 1023;
            int h   = cc >> 6, dd = cc & 63;
            if (sec < 2) {
                float invf = __expf(-(float)(dd >> 1) * RC);
                float scl = (sec == 0) ? 0.125f : 1.f;
                __half* dst = (sec == 0) ? Qd : Kd;
#pragma unroll
                for (int mf = 0; mf < 4; ++mf) {
                    int row = m0 + wm + (mf << 4) + tr;
#pragma unroll
                    for (int hf = 0; hf < 2; ++hf) {
                        int rr = row + (hf << 3);
                        int b = rr >> 11, sxx = rr & 2047;
                        float ph = (float)sxx * invf;
                        float co, si;
                        __sincosf(ph, &si, &co);
                        float x1 = acc[mf][nf][hf * 2], x2 = acc[mf][nf][hf * 2 + 1];
                        __half2 hp = {__float2half((x1 * co - x2 * si) * scl),
                                      __float2half((x1 * si + x2 * co) * scl)};
                        *(__half2*)(dst + (((size_t)(b * NH + h) * SS + sxx) << 6) + dd) = hp;
                    }
                }
            } else {
#pragma unroll
                for (int mf = 0; mf < 4; ++mf) {
                    int row = m0 + wm + (mf << 4) + tr;
#pragma unroll
                    for (int hf = 0; hf < 2; ++hf) {
                        int rr = row + (hf << 3);
                        int b = rr >> 11, sxx = rr & 2047;
                        __half2 hp = {__float2half(acc[mf][nf][hf * 2]),
                                      __float2half(acc[mf][nf][hf * 2 + 1])};
                        *(__half2*)(Vd + (((size_t)(b * NH + h) * SS + sxx) << 6) + dd) = hp;
                    }
                }
            }
        }
    }
}

// ---------------- merged fp32 -> fp16 conversions (one kernel, MLP=4) -------
#define CN0 (MTOT*DIMV/4)
#define CN1 (3*DIMV*DIMV/4)
#define CN2 (DIMV*DIMV/4)
#define CN3 (FFV*DIMV/4)
#define CN4 (DIMV*FFV/4)
#define CNT (CN0+CN1+CN2+CN3+CN4)
#define CITEMS 4
#define CTHREADS ((CNT + CITEMS - 1) / CITEMS)

__device__ __forceinline__ void conv_item(
    int idx,
    const float* __restrict__ x,      __half* __restrict__ xb,
    const float* __restrict__ qkvw,   __half* __restrict__ wqkv,
    const float* __restrict__ aow,    __half* __restrict__ wao,
    const float* __restrict__ gw, const float* __restrict__ lw,
    __half* __restrict__ wgl,
    const float* __restrict__ fow,    __half* __restrict__ wfo)
{
    if (idx < CN0) {
        *(uint2*)(xb + 4 * (size_t)idx) = pack4(*(const float4*)(x + 4 * (size_t)idx));
        return;
    }
    idx -= CN0;
    if (idx < CN1) {
        int row = idx >> 8, c4 = (idx & 255) << 2;
        int sec = row >> 10, within = row & 1023;
        int nrow = row;
        if (sec < 2) {
            int h = within >> 6, d = within & 63;
            nrow = (sec << 10) + (h << 6) + ((d & 31) << 1) + (d >> 5);
        }
        float4 v = *(const float4*)(qkvw + (size_t)row * DIMV + c4);
        *(uint2*)(wqkv + (size_t)nrow * KP1 + c4) = pack4(v);
        return;
    }
    idx -= CN1;
    if (idx < CN2) {
        *(uint2*)(wao + 4 * (size_t)idx) = pack4(*(const float4*)(aow + 4 * (size_t)idx));
        return;
    }
    idx -= CN2;
    if (idx < CN3) {
        int row = idx >> 8, c4 = (idx & 255) << 2;
        size_t src = (size_t)row * DIMV + c4;
        size_t bg  = (size_t)(2 * row) * KP1 + c4;
        *(uint2*)(wgl + bg)       = pack4(*(const float4*)(gw + src));
        *(uint2*)(wgl + bg + KP1) = pack4(*(const float4*)(lw + src));
        return;
    }
    idx -= CN3;
    if (idx < CN4) {
        *(uint2*)(wfo + 4 * (size_t)idx) = pack4(*(const float4*)(fow + 4 * (size_t)idx));
    }
}

__global__ void convert_all(
    const float* __restrict__ x,      __half* __restrict__ xb,
    const float* __restrict__ qkvw,   __half* __restrict__ wqkv,
    const float* __restrict__ aow,    __half* __restrict__ wao,
    const float* __restrict__ gw, const float* __restrict__ lw,
    __half* __restrict__ wgl,
    const float* __restrict__ fow,    __half* __restrict__ wfo)
{
    int base = blockIdx.x * blockDim.x + threadIdx.x;
#pragma unroll
    for (int it = 0; it < CITEMS; ++it) {
        int idx = base + it * CTHREADS;
        if (idx < CNT)
            conv_item(idx, x, xb, qkvw, wqkv, aow, wao, gw, lw, wgl, fow, wfo);
    }
}

// ---------------- flash attention, f16 HMMA (64-q CTAs) ----------------------
__global__ void __launch_bounds__(128) attn_mma(
    const __half* __restrict__ qs, const __half* __restrict__ ks,
    const __half* __restrict__ vs, __half* __restrict__ ctxb)
{
    __shared__ __align__(16) char sm[40960];   // Q 8KB | 2 x (K 8KB + V 8KB)
    const uint32_t Qs = smem_u32(sm);
    const uint32_t Ss = Qs + 8192;
    const int qt = gridDim.x - 1 - blockIdx.x;  // heavy tiles first
    const int h = blockIdx.y, b = blockIdx.z;
    const int q0 = qt << 6;
    const int tid = threadIdx.x, wid = tid >> 5, lane = tid & 31;
    const int quad = lane >> 3, l8 = lane & 7;
    const int tr = lane >> 2, tc = (lane & 3) << 1;
    const int wq0 = wid << 4;
    const size_t bh = (size_t)(b * NH + h);
    const __half* qrow = qs + (bh * SS + q0) * 64;
    const __half* krow = ks + bh * SS * 64;
    const __half* vrow = vs + bh * SS * 64;

    for (int c = tid; c < 512; c += 128) {
        int r = c >> 3, kc = c & 7;
        cpa16(Qs + r * 128 + ((kc ^ (r & 7)) << 4),
              (const char*)(qrow + (size_t)r * 64) + kc * 16);
    }
    CP_COMMIT();

    auto load_stage = [&](int kt) {
        uint32_t Kst = Ss + (kt & 1) * 16384, Vst = Kst + 8192;
        const __half* kr = krow + ((size_t)kt << 6) * 64;
        const __half* vr = vrow + ((size_t)kt << 6) * 64;
        for (int c = tid; c < 512; c += 128) {
            int r = c >> 3, kc = c & 7;
            cpa16(Kst + r * 128 + ((kc ^ (r & 7)) << 4),
                  (const char*)(kr + (size_t)r * 64) + kc * 16);
        }
        for (int c = tid; c < 512; c += 128) {
            int r = c >> 3, kc = c & 7;
            cpa16(Vst + r * 128 + ((kc ^ (r & 7)) << 4),
                  (const char*)(vr + (size_t)r * 64) + kc * 16);
        }
        CP_COMMIT();
    };

    float m0r = -1e30f, m1r = -1e30f, l0 = 0.f, l1 = 0.f;
    float oacc[8][4];
#pragma unroll
    for (int i = 0; i < 8; ++i)
#pragma unroll
        for (int j = 0; j < 4; ++j) oacc[i][j] = 0.f;

    const int nt = qt + 1;
    load_stage(0);

    for (int kt = 0; kt < nt; ++kt) {
        if (kt + 1 < nt) {
            load_stage(kt + 1);
            asm volatile("cp.async.wait_group 1;" ::: "memory");
        } else {
            asm volatile("cp.async.wait_group 0;" ::: "memory");
        }
        __syncthreads();
        const uint32_t Kst = Ss + (kt & 1) * 16384, Vst = Kst + 8192;

        float sacc[8][4];
#pragma unroll
        for (int i = 0; i < 8; ++i)
#pragma unroll
            for (int j = 0; j < 4; ++j) sacc[i][j] = 0.f;
#pragma unroll
        for (int ksp = 0; ksp < 4; ++ksp) {
            uint32_t a[4];
            {
                int r = wq0 + ((quad & 1) << 3) + l8;
                int kc = 2 * ksp + (quad >> 1);
                LDSM4(a, Qs + r * 128 + ((kc ^ (r & 7)) << 4));
            }
#pragma unroll
            for (int np = 0; np < 4; ++np) {
                uint32_t bf[4];
                int r = (np << 4) + ((quad >> 1) << 3) + l8;
                int kc = 2 * ksp + (quad & 1);
                LDSM4(bf, Kst + r * 128 + ((kc ^ (r & 7)) << 4));
                MMAF16(sacc[2 * np],     a, bf[0], bf[1]);
                MMAF16(sacc[2 * np + 1], a, bf[2], bf[3]);
            }
        }

        if (kt == qt) {
            int r0 = wq0 + tr, r1 = r0 + 8;
#pragma unroll
            for (int nf = 0; nf < 8; ++nf) {
                int c0 = (nf << 3) + tc;
                if (c0     > r0) sacc[nf][0] = -1e30f;
                if (c0 + 1 > r0) sacc[nf][1] = -1e30f;
                if (c0     > r1) sacc[nf][2] = -1e30f;
                if (c0 + 1 > r1) sacc[nf][3] = -1e30f;
            }
        }

        float mx0 = -1e30f, mx1 = -1e30f;
#pragma unroll
        for (int nf = 0; nf < 8; ++nf) {
            mx0 = fmaxf(mx0, fmaxf(sacc[nf][0], sacc[nf][1]));
            mx1 = fmaxf(mx1, fmaxf(sacc[nf][2], sacc[nf][3]));
        }
        mx0 = fmaxf(mx0, __shfl_xor_sync(0xffffffffu, mx0, 1));
        mx0 = fmaxf(mx0, __shfl_xor_sync(0xffffffffu, mx0, 2));
        mx1 = fmaxf(mx1, __shfl_xor_sync(0xffffffffu, mx1, 1));
        mx1 = fmaxf(mx1, __shfl_xor_sync(0xffffffffu, mx1, 2));
        float mn0 = fmaxf(m0r, mx0), mn1 = fmaxf(m1r, mx1);
        float al0 = __expf(m0r - mn0), al1 = __expf(m1r - mn1);
        float rs0 = 0.f, rs1 = 0.f;
#pragma unroll
        for (int nf = 0; nf < 8; ++nf) {
            sacc[nf][0] = __expf(sacc[nf][0] - mn0);
            sacc[nf][1] = __expf(sacc[nf][1] - mn0);
            sacc[nf][2] = __expf(sacc[nf][2] - mn1);
            sacc[nf][3] = __expf(sacc[nf][3] - mn1);
            rs0 += sacc[nf][0] + sacc[nf][1];
            rs1 += sacc[nf][2] + sacc[nf][3];
        }
        rs0 += __shfl_xor_sync(0xffffffffu, rs0, 1);
        rs0 += __shfl_xor_sync(0xffffffffu, rs0, 2);
        rs1 += __shfl_xor_sync(0xffffffffu, rs1, 1);
        rs1 += __shfl_xor_sync(0xffffffffu, rs1, 2);
        l0 = l0 * al0 + rs0;
        l1 = l1 * al1 + rs1;
        m0r = mn0; m1r = mn1;
#pragma unroll
        for (int nf = 0; nf < 8; ++nf) {
            oacc[nf][0] *= al0; oacc[nf][1] *= al0;
            oacc[nf][2] *= al1; oacc[nf][3] *= al1;
        }

#pragma unroll
        for (int ksp = 0; ksp < 4; ++ksp) {
            uint32_t pa[4];
            pa[0] = pkf16(sacc[2 * ksp][0],     sacc[2 * ksp][1]);
            pa[1] = pkf16(sacc[2 * ksp][2],     sacc[2 * ksp][3]);
            pa[2] = pkf16(sacc[2 * ksp + 1][0], sacc[2 * ksp + 1][1]);
            pa[3] = pkf16(sacc[2 * ksp + 1][2], sacc[2 * ksp + 1][3]);
#pragma unroll
            for (int np = 0; np < 4; ++np) {
                uint32_t bf[4];
                int r  = (ksp << 4) + ((quad & 1) << 3) + l8;
                int kc = 2 * np + (quad >> 1);
                LDSM4T(bf, Vst + r * 128 + ((kc ^ (r & 7)) << 4));
                MMAF16(oacc[2 * np],     pa, bf[0], bf[1]);
                MMAF16(oacc[2 * np + 1], pa, bf[2], bf[3]);
            }
        }
        __syncthreads();
    }

    float i0 = 1.f / l0, i1 = 1.f / l1;
    int row0 = q0 + wq0 + tr;
    __half* p0 = ctxb + ((size_t)b * SS + row0) * KP1 + h * 64;
    __half* p1 = p0 + (size_t)8 * KP1;
#pragma unroll
    for (int nf = 0; nf < 8; ++nf) {
        int co = (nf << 3) + tc;
        __half2 hp0 = {__float2half_rn(oacc[nf][0] * i0),
                       __float2half_rn(oacc[nf][1] * i0)};
        __half2 hp1 = {__float2half_rn(oacc[nf][2] * i1),
                       __float2half_rn(oacc[nf][3] * i1)};
        *(__half2*)(p0 + co) = hp0;
        *(__half2*)(p1 + co) = hp1;
    }
}

// ---------------- out = rms_norm(a + b) * scale  (+ optional fp16 out) ------
__global__ __launch_bounds__(256) void addnorm_kernel(
    const float* __restrict__ a, const float* __restrict__ bbuf,
    const float* __restrict__ scale, float* __restrict__ out,
    __half* __restrict__ outb)
{
    const int row = blockIdx.x;
    const int tid = threadIdx.x;
    const size_t base = (size_t)row * DIMV;
    float4 av = *(const float4*)(a + base + 4 * tid);
    float4 bv = *(const float4*)(bbuf + base + 4 * tid);
    float4 v = make_float4(av.x + bv.x, av.y + bv.y, av.z + bv.z, av.w + bv.w);
    float ss = fmaf(v.x, v.x, fmaf(v.y, v.y, fmaf(v.z, v.z, v.w * v.w)));
    __shared__ float red[8];
#pragma unroll
    for (int o = 16; o; o >>= 1) ss += __shfl_xor_sync(0xffffffffu, ss, o);
    if ((tid & 31) == 0) red[tid >> 5] = ss;
    __syncthreads();
    if (tid < 8) {
        float t = red[tid];
#pragma unroll
        for (int o = 4; o; o >>= 1) t += __shfl_xor_sync(0xffu, t, o);
        if (tid == 0) red[0] = t;
    }
    __syncthreads();
    float rms = sqrtf(red[0] * (1.f / 1024.f));
    float inv = 1.f / (rms + 1e-8f);
    float4 sc = *(const float4*)(scale + 4 * tid);
    float4 o4 = make_float4(sc.x * v.x * inv, sc.y * v.y * inv,
                            sc.z * v.z * inv, sc.w * v.w * inv);
    *(float4*)(out + base + 4 * tid) = o4;
    if (outb) *(uint2*)(outb + base + 4 * tid) = pack4(o4);
}

// ---------------- launcher --------------------------------------------------
extern "C" void kernel_launch(void* const* d_in, const int* in_sizes, int n_in,
                              void* d_out, int out_size)
{
    (void)in_sizes; (void)n_in; (void)out_size;
    const float* x          = (const float*)d_in[0];
    const float* qkv_w      = (const float*)d_in[2];
    const float* attn_out_w = (const float*)d_in[3];
    const float* gate_w     = (const float*)d_in[4];
    const float* gate_b     = (const float*)d_in[5];
    const float* lin_w      = (const float*)d_in[6];
    const float* lin_b      = (const float*)d_in[7];
    const float* ff_out_w   = (const float*)d_in[8];
    const float* n1         = (const float*)d_in[9];
    const float* n2         = (const float*)d_in[10];
    float* out = (float*)d_out;

    float *tmp, *x1;
    __half *qsb, *ksb, *vb;
    __half *xb, *ctxb, *x1b, *hb, *wqkv, *wao, *wgl, *wfo;
    cudaGetSymbolAddress((void**)&tmp,  g_tmp);
    cudaGetSymbolAddress((void**)&x1,   g_x1);
    cudaGetSymbolAddress((void**)&qsb,  g_qs);
    cudaGetSymbolAddress((void**)&ksb,  g_ks);
    cudaGetSymbolAddress((void**)&vb,   g_v);
    cudaGetSymbolAddress((void**)&xb,   g_xb);
    cudaGetSymbolAddress((void**)&ctxb, g_ctxb);
    cudaGetSymbolAddress((void**)&x1b,  g_x1b);
    cudaGetSymbolAddress((void**)&hb,   g_hb);
    cudaGetSymbolAddress((void**)&wqkv, g_wqkv);
    cudaGetSymbolAddress((void**)&wao,  g_wao);
    cudaGetSymbolAddress((void**)&wgl,  g_wgl);
    cudaGetSymbolAddress((void**)&wfo,  g_wfo);

    cudaFuncSetAttribute(gemm_mma_t<0>, cudaFuncAttributeMaxDynamicSharedMemorySize, GEMM_SMEM);
    cudaFuncSetAttribute(gemm_mma_t<1>, cudaFuncAttributeMaxDynamicSharedMemorySize, GEMM_SMEM);
    cudaFuncSetAttribute(gemm_mma_t<2>, cudaFuncAttributeMaxDynamicSharedMemorySize, GEMM_SMEM);

    // 0. all fp32 -> fp16 conversions in one kernel (MLP=4 per thread)
    convert_all<<<(CTHREADS + 255)/256, 256>>>(x, xb, qkv_w, wqkv, attn_out_w, wao,
                                               gate_w, lin_w, wgl, ff_out_w, wfo);

    // 1. QKV projection with fused RoPE epilogue -> q/k/v f16 head-major
    gemm_mma_t<2><<<dim3(3*DIMV/128, MTOT/128), 256, GEMM_SMEM>>>(
        xb, wqkv, nullptr, nullptr, nullptr, nullptr, qsb, ksb, vb, 3*DIMV, KP1);
    // 2. flash attention (64-q CTAs, f16 HMMA) -> fp16 ctx
    attn_mma<<<dim3(SS/64, NH, BB), 128>>>(qsb, ksb, vb, ctxb);
    // 3. output projection
    gemm_mma_t<0><<<dim3(DIMV/128, MTOT/128), 256, GEMM_SMEM>>>(
        ctxb, wao, tmp, nullptr, nullptr, nullptr, nullptr, nullptr, nullptr, DIMV, KP1);
    // 4. x1 = rmsnorm(x + proj), also emit fp16
    addnorm_kernel<<<MTOT, 256>>>(x, tmp, n1, x1, x1b);
    // 5. fused gate+lin GEMM with GLU epilogue -> fp16 hb
    gemm_mma_t<1><<<dim3(2*FFV/128, MTOT/128), 256, GEMM_SMEM>>>(
        x1b, wgl, nullptr, hb, gate_b, lin_b, nullptr, nullptr, nullptr, 2*FFV, KP1);
    // 6. ff out
    gemm_mma_t<0><<<dim3(DIMV/128, MTOT/128), 256, GEMM_SMEM>>>(
        hb, wfo, tmp, nullptr, nullptr, nullptr, nullptr, nullptr, nullptr, DIMV, KP2);
    // 7. out = rmsnorm(x1 + ff)
    addnorm_kernel<<<MTOT, 256>>>(x1, tmp, n2, out, nullptr);
}

// round 16
// speedup vs baseline: 1.0096x; 1.0096x over previous
#include <cuda_runtime.h>
#include <cuda_bf16.h>
#include <cuda_fp16.h>
#include <cstdint>
#include <math.h>

#define BB 2
#define SS 2048
#define DIMV 1024
#define NH 16
#define FFV 4096
#define MTOT (BB*SS)          /* 4096 rows */
#define KP1 DIMV              /* 1024: plain fp16, K = 1024 */
#define KP2 FFV               /* 4096: plain fp16, K = 4096 */

// ---------------- scratch (device globals: allocation-free) ----------------
__device__ float g_tmp[MTOT * DIMV];
__device__ float g_x1 [MTOT * DIMV];

__device__ __align__(16) __half g_qs[(size_t)BB * NH * SS * 64];
__device__ __align__(16) __half g_ks[(size_t)BB * NH * SS * 64];
__device__ __align__(16) __half g_v [(size_t)BB * NH * SS * 64];

__device__ __align__(16) __half g_xb  [MTOT * KP1];
__device__ __align__(16) __half g_ctxb[MTOT * KP1];
__device__ __align__(16) __half g_x1b [MTOT * KP1];
__device__ __align__(16) __half g_hb  [(size_t)MTOT * KP2];
__device__ __align__(16) __half g_wqkv[3 * DIMV * KP1];
__device__ __align__(16) __half g_wao [DIMV * KP1];
__device__ __align__(16) __half g_wgl [(size_t)2 * FFV * KP1];  // interleaved gate/lin
__device__ __align__(16) __half g_wfo [DIMV * KP2];

// ---------------- PTX helpers ----------------------------------------------
__device__ __forceinline__ uint32_t smem_u32(const void* p) {
    uint32_t a;
    asm("{ .reg .u64 t; cvta.to.shared.u64 t, %1; cvt.u32.u64 %0, t; }"
        : "=r"(a) : "l"(p));
    return a;
}
__device__ __forceinline__ void cpa16(uint32_t dst, const void* src) {
    asm volatile("cp.async.cg.shared.global [%0], [%1], 16;" :: "r"(dst), "l"(src));
}
#define CP_COMMIT() asm volatile("cp.async.commit_group;" ::: "memory")

#define LDSM4(r, addr) \
    asm volatile("ldmatrix.sync.aligned.m8n8.x4.shared.b16 {%0,%1,%2,%3}, [%4];" \
        : "=r"((r)[0]), "=r"((r)[1]), "=r"((r)[2]), "=r"((r)[3]) : "r"(addr))

#define LDSM4T(r, addr) \
    asm volatile("ldmatrix.sync.aligned.m8n8.x4.trans.shared.b16 {%0,%1,%2,%3}, [%4];" \
        : "=r"((r)[0]), "=r"((r)[1]), "=r"((r)[2]), "=r"((r)[3]) : "r"(addr))

#define MMAF16(d, a, b0, b1) \
    asm volatile("mma.sync.aligned.m16n8k16.row.col.f32.f16.f16.f32 " \
        "{%0,%1,%2,%3},{%4,%5,%6,%7},{%8,%9},{%0,%1,%2,%3};" \
        : "+f"((d)[0]), "+f"((d)[1]), "+f"((d)[2]), "+f"((d)[3]) \
        : "r"((a)[0]), "r"((a)[1]), "r"((a)[2]), "r"((a)[3]), "r"(b0), "r"(b1))

__device__ __forceinline__ uint32_t pkf16(float lo, float hi) {
    uint32_t r;
    asm("cvt.rn.f16x2.f32 %0, %1, %2;" : "=r"(r) : "f"(hi), "f"(lo));
    return r;
}
__device__ __forceinline__ uint2 pack4(float4 v) {
    uint2 u;
    u.x = pkf16(v.x, v.y);
    u.y = pkf16(v.z, v.w);
    return u;
}

// ---------------- fp16 HMMA GEMM: C[M,N] = A[M,Kp] @ W[N,Kp]^T --------------
// CTA 128x128, 8 warps (2x4), warp 64x32, BK=64, 3-stage cp.async pipeline.
// EPI=0: plain fp32 store.
// EPI=1: GLU epilogue -> fp16 HB over KP2.
// EPI=2: QKV epilogue: q/k RoPE (paired cols, fast trig) -> f16 head-major.
#define GSTAGES 3
#define GSTAGE_BYTES 32768          /* A 16KB + B 16KB */
#define GEMM_SMEM (GSTAGES * GSTAGE_BYTES)

template<int EPI>
__global__ void __launch_bounds__(256) gemm_mma_t(
    const __half* __restrict__ A, const __half* __restrict__ W,
    float* __restrict__ C, __half* __restrict__ HB,
    const float* __restrict__ gb, const float* __restrict__ lb,
    __half* __restrict__ Qd, __half* __restrict__ Kd, __half* __restrict__ Vd,
    int N, int Kp)
{
    extern __shared__ char sm[];
    const uint32_t smb = smem_u32(sm);
    const int tid  = threadIdx.x;
    const int wid  = tid >> 5, lane = tid & 31;
    const int wm   = (wid >> 2) << 6;
    const int wn   = (wid & 3) << 5;
    const int m0   = blockIdx.y << 7, n0 = blockIdx.x << 7;
    const int quad = lane >> 3, l8 = lane & 7;

    float acc[4][4][4];
#pragma unroll
    for (int i = 0; i < 4; ++i)
#pragma unroll
        for (int j = 0; j < 4; ++j)
#pragma unroll
            for (int v = 0; v < 4; ++v) acc[i][j][v] = 0.f;

    auto load_stage = [&](int kt) {
        const int s = kt % GSTAGES;
        const uint32_t sa = smb + s * GSTAGE_BYTES;
        const uint32_t sb = sa + 16384;
        const size_t kbase = (size_t)kt << 6;
#pragma unroll
        for (int p = 0; p < 4; ++p) {
            int chunk = (p << 8) + tid;
            int r = chunk >> 3, kc = chunk & 7;
            cpa16(sa + r * 128 + ((kc ^ (r & 7)) << 4),
                  (const char*)(A + (size_t)(m0 + r) * Kp + kbase + kc * 8));
        }
#pragma unroll
        for (int p = 0; p < 4; ++p) {
            int chunk = (p << 8) + tid;
            int r = chunk >> 3, kc = chunk & 7;
            cpa16(sb + r * 128 + ((kc ^ (r & 7)) << 4),
                  (const char*)(W + (size_t)(n0 + r) * Kp + kbase + kc * 8));
        }
        CP_COMMIT();
    };

    const int nk = Kp >> 6;
    load_stage(0);
    load_stage(1);

    for (int kt = 0; kt < nk; ++kt) {
        const int s = kt % GSTAGES;
        asm volatile("cp.async.wait_group 1;" ::: "memory");
        __syncthreads();
        if (kt + 2 < nk) load_stage(kt + 2); else CP_COMMIT();

        const uint32_t sa = smb + s * GSTAGE_BYTES;
        const uint32_t sb = sa + 16384;
#pragma unroll
        for (int ks = 0; ks < 4; ++ks) {
            const int k0c = ks << 1;
            uint32_t a[4][4], b[2][4];
#pragma unroll
            for (int mf = 0; mf < 4; ++mf) {
                int r  = wm + (mf << 4) + ((quad & 1) << 3) + l8;
                int kc = k0c + (quad >> 1);
                LDSM4(a[mf], sa + r * 128 + ((kc ^ (r & 7)) << 4));
            }
#pragma unroll
            for (int np = 0; np < 2; ++np) {
                int r  = wn + (np << 4) + ((quad >> 1) << 3) + l8;
                int kc = k0c + (quad & 1);
                LDSM4(b[np], sb + r * 128 + ((kc ^ (r & 7)) << 4));
            }
#pragma unroll
            for (int mf = 0; mf < 4; ++mf) {
#pragma unroll
                for (int np = 0; np < 2; ++np) {
                    MMAF16(acc[mf][2 * np],     a[mf], b[np][0], b[np][1]);
                    MMAF16(acc[mf][2 * np + 1], a[mf], b[np][2], b[np][3]);
                }
            }
        }
    }

    const int tr = lane >> 2, tc = (lane & 3) << 1;
    if (EPI == 0) {
#pragma unroll
        for (int mf = 0; mf < 4; ++mf) {
            int row = m0 + wm + (mf << 4) + tr;
            float* c0 = C + (size_t)row * N + n0 + wn;
            float* c1 = c0 + (size_t)8 * N;
#pragma unroll
            for (int nf = 0; nf < 4; ++nf) {
                *(float2*)(c0 + (nf << 3) + tc) = make_float2(acc[mf][nf][0], acc[mf][nf][1]);
                *(float2*)(c1 + (nf << 3) + tc) = make_float2(acc[mf][nf][2], acc[mf][nf][3]);
            }
        }
    } else if (EPI == 1) {
        // interleaved cols: even col = gate_c, odd col = lin_c, c = gcol>>1.
#pragma unroll
        for (int mf = 0; mf < 4; ++mf) {
            int row0 = m0 + wm + (mf << 4) + tr;
#pragma unroll
            for (int nf = 0; nf < 4; ++nf) {
                int c = (n0 + wn + (nf << 3) + tc) >> 1;
                float gbv = gb[c], lbv = lb[c];
                float h0 = (acc[mf][nf][1] + lbv) *
                           (1.f / (1.f + __expf(-(acc[mf][nf][0] + gbv))));
                float h1 = (acc[mf][nf][3] + lbv) *
                           (1.f / (1.f + __expf(-(acc[mf][nf][2] + gbv))));
                float h0p = __shfl_xor_sync(0xffffffffu, h0, 1);
                float h1p = __shfl_xor_sync(0xffffffffu, h1, 1);
                if ((lane & 1) == 0) {
                    __half2 hi0 = {__float2half_rn(h0), __float2half_rn(h0p)};
                    __half2 hi1 = {__float2half_rn(h1), __float2half_rn(h1p)};
                    __half* p0 = HB + (size_t)row0 * KP2 + c;
                    __half* p1 = p0 + (size_t)8 * KP2;
                    *(__half2*)(p0) = hi0;
                    *(__half2*)(p1) = hi1;
                }
            }
        }
    } else {
        // EPI == 2: QKV epilogue. Permuted weight rows -> thread holds RoPE
        // pair (x1_j, x2_j) in adjacent cols. q/k stored head-major f16.
        const float RC = 9.210340371976184f / 32.0f;
#pragma unroll
        for (int nf = 0; nf < 4; ++nf) {
            int col = n0 + wn + (nf << 3) + tc;   // even
            int sec = col >> 10;
            int cc  = col & 1023;
            int h   = cc >> 6, dd = cc & 63;
            if (sec < 2) {
                float invf = __expf(-(float)(dd >> 1) * RC);
                float scl = (sec == 0) ? 0.125f : 1.f;
                __half* dst = (sec == 0) ? Qd : Kd;
#pragma unroll
                for (int mf = 0; mf < 4; ++mf) {
                    int row = m0 + wm + (mf << 4) + tr;
#pragma unroll
                    for (int hf = 0; hf < 2; ++hf) {
                        int rr = row + (hf << 3);
                        int b = rr >> 11, sxx = rr & 2047;
                        float ph = (float)sxx * invf;
                        float co, si;
                        __sincosf(ph, &si, &co);
                        float x1 = acc[mf][nf][hf * 2], x2 = acc[mf][nf][hf * 2 + 1];
                        __half2 hp = {__float2half((x1 * co - x2 * si) * scl),
                                      __float2half((x1 * si + x2 * co) * scl)};
                        *(__half2*)(dst + (((size_t)(b * NH + h) * SS + sxx) << 6) + dd) = hp;
                    }
                }
            } else {
#pragma unroll
                for (int mf = 0; mf < 4; ++mf) {
                    int row = m0 + wm + (mf << 4) + tr;
#pragma unroll
                    for (int hf = 0; hf < 2; ++hf) {
                        int rr = row + (hf << 3);
                        int b = rr >> 11, sxx = rr & 2047;
                        __half2 hp = {__float2half(acc[mf][nf][hf * 2]),
                                      __float2half(acc[mf][nf][hf * 2 + 1])};
                        *(__half2*)(Vd + (((size_t)(b * NH + h) * SS + sxx) << 6) + dd) = hp;
                    }
                }
            }
        }
    }
}

// ---------------- merged fp32 -> fp16 conversions (one kernel, MLP=4) -------
#define CN0 (MTOT*DIMV/4)
#define CN1 (3*DIMV*DIMV/4)
#define CN2 (DIMV*DIMV/4)
#define CN3 (FFV*DIMV/4)
#define CN4 (DIMV*FFV/4)
#define CNT (CN0+CN1+CN2+CN3+CN4)
#define CITEMS 4
#define CTHREADS ((CNT + CITEMS - 1) / CITEMS)

__device__ __forceinline__ void conv_item(
    int idx,
    const float* __restrict__ x,      __half* __restrict__ xb,
    const float* __restrict__ qkvw,   __half* __restrict__ wqkv,
    const float* __restrict__ aow,    __half* __restrict__ wao,
    const float* __restrict__ gw, const float* __restrict__ lw,
    __half* __restrict__ wgl,
    const float* __restrict__ fow,    __half* __restrict__ wfo)
{
    if (idx < CN0) {
        *(uint2*)(xb + 4 * (size_t)idx) = pack4(*(const float4*)(x + 4 * (size_t)idx));
        return;
    }
    idx -= CN0;
    if (idx < CN1) {
        int row = idx >> 8, c4 = (idx & 255) << 2;
        int sec = row >> 10, within = row & 1023;
        int nrow = row;
        if (sec < 2) {
            int h = within >> 6, d = within & 63;
            nrow = (sec << 10) + (h << 6) + ((d & 31) << 1) + (d >> 5);
        }
        float4 v = *(const float4*)(qkvw + (size_t)row * DIMV + c4);
        *(uint2*)(wqkv + (size_t)nrow * KP1 + c4) = pack4(v);
        return;
    }
    idx -= CN1;
    if (idx < CN2) {
        *(uint2*)(wao + 4 * (size_t)idx) = pack4(*(const float4*)(aow + 4 * (size_t)idx));
        return;
    }
    idx -= CN2;
    if (idx < CN3) {
        int row = idx >> 8, c4 = (idx & 255) << 2;
        size_t src = (size_t)row * DIMV + c4;
        size_t bg  = (size_t)(2 * row) * KP1 + c4;
        *(uint2*)(wgl + bg)       = pack4(*(const float4*)(gw + src));
        *(uint2*)(wgl + bg + KP1) = pack4(*(const float4*)(lw + src));
        return;
    }
    idx -= CN3;
    if (idx < CN4) {
        *(uint2*)(wfo + 4 * (size_t)idx) = pack4(*(const float4*)(fow + 4 * (size_t)idx));
    }
}

__global__ void convert_all(
    const float* __restrict__ x,      __half* __restrict__ xb,
    const float* __restrict__ qkvw,   __half* __restrict__ wqkv,
    const float* __restrict__ aow,    __half* __restrict__ wao,
    const float* __restrict__ gw, const float* __restrict__ lw,
    __half* __restrict__ wgl,
    const float* __restrict__ fow,    __half* __restrict__ wfo)
{
    int base = blockIdx.x * blockDim.x + threadIdx.x;
#pragma unroll
    for (int it = 0; it < CITEMS; ++it) {
        int idx = base + it * CTHREADS;
        if (idx < CNT)
            conv_item(idx, x, xb, qkvw, wqkv, aow, wao, gw, lw, wgl, fow, wfo);
    }
}

// ---------------- flash attention, f16 HMMA ---------------------------------
// CTA = 64 q-rows, 4 warps. K/V staged in 128-row tiles (double-buffered,
// dynamic smem 72KB -> 3 CTAs/SM). Softmax once per 128 cols; masked tail.
#define ATT_SMEM (8192 + 2 * 32768)

__global__ void __launch_bounds__(128) attn_mma(
    const __half* __restrict__ qs, const __half* __restrict__ ks,
    const __half* __restrict__ vs, __half* __restrict__ ctxb)
{
    extern __shared__ __align__(16) char sm[];
    const uint32_t Qs = smem_u32(sm);
    const uint32_t Ss = Qs + 8192;
    const int qt = gridDim.x - 1 - blockIdx.x;  // heavy tiles first
    const int h = blockIdx.y, b = blockIdx.z;
    const int q0 = qt << 6;
    const int tid = threadIdx.x, wid = tid >> 5, lane = tid & 31;
    const int quad = lane >> 3, l8 = lane & 7;
    const int tr = lane >> 2, tc = (lane & 3) << 1;
    const int wq0 = wid << 4;
    const size_t bh = (size_t)(b * NH + h);
    const __half* qrow = qs + (bh * SS + q0) * 64;
    const __half* krow = ks + bh * SS * 64;
    const __half* vrow = vs + bh * SS * 64;

    for (int c = tid; c < 512; c += 128) {
        int r = c >> 3, kc = c & 7;
        cpa16(Qs + r * 128 + ((kc ^ (r & 7)) << 4),
              (const char*)(qrow + (size_t)r * 64) + kc * 16);
    }
    CP_COMMIT();

    // k-tiles are 128 rows wide
    auto load_stage = [&](int kt) {
        uint32_t Kst = Ss + (kt & 1) * 32768, Vst = Kst + 16384;
        const __half* kr = krow + ((size_t)kt << 7) * 64;
        const __half* vr = vrow + ((size_t)kt << 7) * 64;
        for (int c = tid; c < 1024; c += 128) {
            int r = c >> 3, kc = c & 7;
            cpa16(Kst + r * 128 + ((kc ^ (r & 7)) << 4),
                  (const char*)(kr + (size_t)r * 64) + kc * 16);
        }
        for (int c = tid; c < 1024; c += 128) {
            int r = c >> 3, kc = c & 7;
            cpa16(Vst + r * 128 + ((kc ^ (r & 7)) << 4),
                  (const char*)(vr + (size_t)r * 64) + kc * 16);
        }
        CP_COMMIT();
    };

    float m0r = -1e30f, m1r = -1e30f, l0 = 0.f, l1 = 0.f;
    float oacc[8][4];
#pragma unroll
    for (int i = 0; i < 8; ++i)
#pragma unroll
        for (int j = 0; j < 4; ++j) oacc[i][j] = 0.f;

    const int nt = (qt >> 1) + 1;   // 128-row tiles covering [0, q0+64)
    load_stage(0);

    for (int kt = 0; kt < nt; ++kt) {
        if (kt + 1 < nt) {
            load_stage(kt + 1);
            asm volatile("cp.async.wait_group 1;" ::: "memory");
        } else {
            asm volatile("cp.async.wait_group 0;" ::: "memory");
        }
        __syncthreads();
        const uint32_t Kst = Ss + (kt & 1) * 32768, Vst = Kst + 16384;

        // S = Q @ K^T over 128 columns
        float sacc[16][4];
#pragma unroll
        for (int i = 0; i < 16; ++i)
#pragma unroll
            for (int j = 0; j < 4; ++j) sacc[i][j] = 0.f;
#pragma unroll
        for (int ksp = 0; ksp < 4; ++ksp) {
            uint32_t a[4];
            {
                int r = wq0 + ((quad & 1) << 3) + l8;
                int kc = 2 * ksp + (quad >> 1);
                LDSM4(a, Qs + r * 128 + ((kc ^ (r & 7)) << 4));
            }
#pragma unroll
            for (int np = 0; np < 8; ++np) {
                uint32_t bf[4];
                int r = (np << 4) + ((quad >> 1) << 3) + l8;
                int kc = 2 * ksp + (quad & 1);
                LDSM4(bf, Kst + r * 128 + ((kc ^ (r & 7)) << 4));
                MMAF16(sacc[2 * np],     a, bf[0], bf[1]);
                MMAF16(sacc[2 * np + 1], a, bf[2], bf[3]);
            }
        }

        // causal mask on the final tile (covers cols beyond q0+63 too)
        if (kt == nt - 1) {
            int cbase = kt << 7;
            int r0 = q0 + wq0 + tr, r1 = r0 + 8;
#pragma unroll
            for (int nf = 0; nf < 16; ++nf) {
                int c0 = cbase + (nf << 3) + tc;
                if (c0     > r0) sacc[nf][0] = -1e30f;
                if (c0 + 1 > r0) sacc[nf][1] = -1e30f;
                if (c0     > r1) sacc[nf][2] = -1e30f;
                if (c0 + 1 > r1) sacc[nf][3] = -1e30f;
            }
        }

        float mx0 = -1e30f, mx1 = -1e30f;
#pragma unroll
        for (int nf = 0; nf < 16; ++nf) {
            mx0 = fmaxf(mx0, fmaxf(sacc[nf][0], sacc[nf][1]));
            mx1 = fmaxf(mx1, fmaxf(sacc[nf][2], sacc[nf][3]));
        }
        mx0 = fmaxf(mx0, __shfl_xor_sync(0xffffffffu, mx0, 1));
        mx0 = fmaxf(mx0, __shfl_xor_sync(0xffffffffu, mx0, 2));
        mx1 = fmaxf(mx1, __shfl_xor_sync(0xffffffffu, mx1, 1));
        mx1 = fmaxf(mx1, __shfl_xor_sync(0xffffffffu, mx1, 2));
        float mn0 = fmaxf(m0r, mx0), mn1 = fmaxf(m1r, mx1);
        float al0 = __expf(m0r - mn0), al1 = __expf(m1r - mn1);
        float rs0 = 0.f, rs1 = 0.f;
#pragma unroll
        for (int nf = 0; nf < 16; ++nf) {
            sacc[nf][0] = __expf(sacc[nf][0] - mn0);
            sacc[nf][1] = __expf(sacc[nf][1] - mn0);
            sacc[nf][2] = __expf(sacc[nf][2] - mn1);
            sacc[nf][3] = __expf(sacc[nf][3] - mn1);
            rs0 += sacc[nf][0] + sacc[nf][1];
            rs1 += sacc[nf][2] + sacc[nf][3];
        }
        rs0 += __shfl_xor_sync(0xffffffffu, rs0, 1);
        rs0 += __shfl_xor_sync(0xffffffffu, rs0, 2);
        rs1 += __shfl_xor_sync(0xffffffffu, rs1, 1);
        rs1 += __shfl_xor_sync(0xffffffffu, rs1, 2);
        l0 = l0 * al0 + rs0;
        l1 = l1 * al1 + rs1;
        m0r = mn0; m1r = mn1;
#pragma unroll
        for (int nf = 0; nf < 8; ++nf) {
            oacc[nf][0] *= al0; oacc[nf][1] *= al0;
            oacc[nf][2] *= al1; oacc[nf][3] *= al1;
        }

        // O += P @ V over 128 keys: 8 k-steps of 16
#pragma unroll
        for (int ksp = 0; ksp < 8; ++ksp) {
            uint32_t pa[4];
            pa[0] = pkf16(sacc[2 * ksp][0],     sacc[2 * ksp][1]);
            pa[1] = pkf16(sacc[2 * ksp][2],     sacc[2 * ksp][3]);
            pa[2] = pkf16(sacc[2 * ksp + 1][0], sacc[2 * ksp + 1][1]);
            pa[3] = pkf16(sacc[2 * ksp + 1][2], sacc[2 * ksp + 1][3]);
#pragma unroll
            for (int np = 0; np < 4; ++np) {
                uint32_t bf[4];
                int r  = (ksp << 4) + ((quad & 1) << 3) + l8;   // s rows 0..127
                int kc = 2 * np + (quad >> 1);                  // d chunk
                LDSM4T(bf, Vst + r * 128 + ((kc ^ (r & 7)) << 4));
                MMAF16(oacc[2 * np],     pa, bf[0], bf[1]);
                MMAF16(oacc[2 * np + 1], pa, bf[2], bf[3]);
            }
        }
        __syncthreads();
    }

    float i0 = 1.f / l0, i1 = 1.f / l1;
    int row0 = q0 + wq0 + tr;
    __half* p0 = ctxb + ((size_t)b * SS + row0) * KP1 + h * 64;
    __half* p1 = p0 + (size_t)8 * KP1;
#pragma unroll
    for (int nf = 0; nf < 8; ++nf) {
        int co = (nf << 3) + tc;
        __half2 hp0 = {__float2half_rn(oacc[nf][0] * i0),
                       __float2half_rn(oacc[nf][1] * i0)};
        __half2 hp1 = {__float2half_rn(oacc[nf][2] * i1),
                       __float2half_rn(oacc[nf][3] * i1)};
        *(__half2*)(p0 + co) = hp0;
        *(__half2*)(p1 + co) = hp1;
    }
}

// ---------------- out = rms_norm(a + b) * scale  (+ optional fp16 out) ------
__global__ __launch_bounds__(256) void addnorm_kernel(
    const float* __restrict__ a, const float* __restrict__ bbuf,
    const float* __restrict__ scale, float* __restrict__ out,
    __half* __restrict__ outb)
{
    const int row = blockIdx.x;
    const int tid = threadIdx.x;
    const size_t base = (size_t)row * DIMV;
    float4 av = *(const float4*)(a + base + 4 * tid);
    float4 bv = *(const float4*)(bbuf + base + 4 * tid);
    float4 v = make_float4(av.x + bv.x, av.y + bv.y, av.z + bv.z, av.w + bv.w);
    float ss = fmaf(v.x, v.x, fmaf(v.y, v.y, fmaf(v.z, v.z, v.w * v.w)));
    __shared__ float red[8];
#pragma unroll
    for (int o = 16; o; o >>= 1) ss += __shfl_xor_sync(0xffffffffu, ss, o);
    if ((tid & 31) == 0) red[tid >> 5] = ss;
    __syncthreads();
    if (tid < 8) {
        float t = red[tid];
#pragma unroll
        for (int o = 4; o; o >>= 1) t += __shfl_xor_sync(0xffu, t, o);
        if (tid == 0) red[0] = t;
    }
    __syncthreads();
    float rms = sqrtf(red[0] * (1.f / 1024.f));
    float inv = 1.f / (rms + 1e-8f);
    float4 sc = *(const float4*)(scale + 4 * tid);
    float4 o4 = make_float4(sc.x * v.x * inv, sc.y * v.y * inv,
                            sc.z * v.z * inv, sc.w * v.w * inv);
    *(float4*)(out + base + 4 * tid) = o4;
    if (outb) *(uint2*)(outb + base + 4 * tid) = pack4(o4);
}

// ---------------- launcher --------------------------------------------------
extern "C" void kernel_launch(void* const* d_in, const int* in_sizes, int n_in,
                              void* d_out, int out_size)
{
    (void)in_sizes; (void)n_in; (void)out_size;
    const float* x          = (const float*)d_in[0];
    const float* qkv_w      = (const float*)d_in[2];
    const float* attn_out_w = (const float*)d_in[3];
    const float* gate_w     = (const float*)d_in[4];
    const float* gate_b     = (const float*)d_in[5];
    const float* lin_w      = (const float*)d_in[6];
    const float* lin_b      = (const float*)d_in[7];
    const float* ff_out_w   = (const float*)d_in[8];
    const float* n1         = (const float*)d_in[9];
    const float* n2         = (const float*)d_in[10];
    float* out = (float*)d_out;

    float *tmp, *x1;
    __half *qsb, *ksb, *vb;
    __half *xb, *ctxb, *x1b, *hb, *wqkv, *wao, *wgl, *wfo;
    cudaGetSymbolAddress((void**)&tmp,  g_tmp);
    cudaGetSymbolAddress((void**)&x1,   g_x1);
    cudaGetSymbolAddress((void**)&qsb,  g_qs);
    cudaGetSymbolAddress((void**)&ksb,  g_ks);
    cudaGetSymbolAddress((void**)&vb,   g_v);
    cudaGetSymbolAddress((void**)&xb,   g_xb);
    cudaGetSymbolAddress((void**)&ctxb, g_ctxb);
    cudaGetSymbolAddress((void**)&x1b,  g_x1b);
    cudaGetSymbolAddress((void**)&hb,   g_hb);
    cudaGetSymbolAddress((void**)&wqkv, g_wqkv);
    cudaGetSymbolAddress((void**)&wao,  g_wao);
    cudaGetSymbolAddress((void**)&wgl,  g_wgl);
    cudaGetSymbolAddress((void**)&wfo,  g_wfo);

    cudaFuncSetAttribute(gemm_mma_t<0>, cudaFuncAttributeMaxDynamicSharedMemorySize, GEMM_SMEM);
    cudaFuncSetAttribute(gemm_mma_t<1>, cudaFuncAttributeMaxDynamicSharedMemorySize, GEMM_SMEM);
    cudaFuncSetAttribute(gemm_mma_t<2>, cudaFuncAttributeMaxDynamicSharedMemorySize, GEMM_SMEM);
    cudaFuncSetAttribute(attn_mma,      cudaFuncAttributeMaxDynamicSharedMemorySize, ATT_SMEM);

    // 0. all fp32 -> fp16 conversions in one kernel (MLP=4 per thread)
    convert_all<<<(CTHREADS + 255)/256, 256>>>(x, xb, qkv_w, wqkv, attn_out_w, wao,
                                               gate_w, lin_w, wgl, ff_out_w, wfo);

    // 1. QKV projection with fused RoPE epilogue -> q/k/v f16 head-major
    gemm_mma_t<2><<<dim3(3*DIMV/128, MTOT/128), 256, GEMM_SMEM>>>(
        xb, wqkv, nullptr, nullptr, nullptr, nullptr, qsb, ksb, vb, 3*DIMV, KP1);
    // 2. flash attention (64-q CTAs, 128-key tiles) -> fp16 ctx
    attn_mma<<<dim3(SS/64, NH, BB), 128, ATT_SMEM>>>(qsb, ksb, vb, ctxb);
    // 3. output projection
    gemm_mma_t<0><<<dim3(DIMV/128, MTOT/128), 256, GEMM_SMEM>>>(
        ctxb, wao, tmp, nullptr, nullptr, nullptr, nullptr, nullptr, nullptr, DIMV, KP1);
    // 4. x1 = rmsnorm(x + proj), also emit fp16
    addnorm_kernel<<<MTOT, 256>>>(x, tmp, n1, x1, x1b);
    // 5. fused gate+lin GEMM with GLU epilogue -> fp16 hb
    gemm_mma_t<1><<<dim3(2*FFV/128, MTOT/128), 256, GEMM_SMEM>>>(
        x1b, wgl, nullptr, hb, gate_b, lin_b, nullptr, nullptr, nullptr, 2*FFV, KP1);
    // 6. ff out
    gemm_mma_t<0><<<dim3(DIMV/128, MTOT/128), 256, GEMM_SMEM>>>(
        hb, wfo, tmp, nullptr, nullptr, nullptr, nullptr, nullptr, nullptr, DIMV, KP2);
    // 7. out = rmsnorm(x1 + ff)
    addnorm_kernel<<<MTOT, 256>>>(x1, tmp, n2, out, nullptr);
}

// round 17
// speedup vs baseline: 1.0140x; 1.0043x over previous
#include <cuda_runtime.h>
#include <cuda_bf16.h>
#include <cuda_fp16.h>
#include <cstdint>
#include <math.h>

#define BB 2
#define SS 2048
#define DIMV 1024
#define NH 16
#define FFV 4096
#define MTOT (BB*SS)          /* 4096 rows */
#define KP1 DIMV              /* 1024: plain fp16, K = 1024 */
#define KP2 FFV               /* 4096: plain fp16, K = 4096 */

// ---------------- scratch (device globals: allocation-free) ----------------
__device__ __align__(16) __half g_tmph[MTOT * DIMV];   // fp16 projection outputs

__device__ __align__(16) __half g_qs[(size_t)BB * NH * SS * 64];
__device__ __align__(16) __half g_ks[(size_t)BB * NH * SS * 64];
__device__ __align__(16) __half g_v [(size_t)BB * NH * SS * 64];

__device__ __align__(16) __half g_xb  [MTOT * KP1];
__device__ __align__(16) __half g_ctxb[MTOT * KP1];
__device__ __align__(16) __half g_x1b [MTOT * KP1];
__device__ __align__(16) __half g_hb  [(size_t)MTOT * KP2];
__device__ __align__(16) __half g_wqkv[3 * DIMV * KP1];
__device__ __align__(16) __half g_wao [DIMV * KP1];
__device__ __align__(16) __half g_wgl [(size_t)2 * FFV * KP1];  // interleaved gate/lin
__device__ __align__(16) __half g_wfo [DIMV * KP2];

// ---------------- PTX helpers ----------------------------------------------
__device__ __forceinline__ uint32_t smem_u32(const void* p) {
    uint32_t a;
    asm("{ .reg .u64 t; cvta.to.shared.u64 t, %1; cvt.u32.u64 %0, t; }"
        : "=r"(a) : "l"(p));
    return a;
}
__device__ __forceinline__ void cpa16(uint32_t dst, const void* src) {
    asm volatile("cp.async.cg.shared.global [%0], [%1], 16;" :: "r"(dst), "l"(src));
}
#define CP_COMMIT() asm volatile("cp.async.commit_group;" ::: "memory")

#define LDSM4(r, addr) \
    asm volatile("ldmatrix.sync.aligned.m8n8.x4.shared.b16 {%0,%1,%2,%3}, [%4];" \
        : "=r"((r)[0]), "=r"((r)[1]), "=r"((r)[2]), "=r"((r)[3]) : "r"(addr))

#define LDSM4T(r, addr) \
    asm volatile("ldmatrix.sync.aligned.m8n8.x4.trans.shared.b16 {%0,%1,%2,%3}, [%4];" \
        : "=r"((r)[0]), "=r"((r)[1]), "=r"((r)[2]), "=r"((r)[3]) : "r"(addr))

#define MMAF16(d, a, b0, b1) \
    asm volatile("mma.sync.aligned.m16n8k16.row.col.f32.f16.f16.f32 " \
        "{%0,%1,%2,%3},{%4,%5,%6,%7},{%8,%9},{%0,%1,%2,%3};" \
        : "+f"((d)[0]), "+f"((d)[1]), "+f"((d)[2]), "+f"((d)[3]) \
        : "r"((a)[0]), "r"((a)[1]), "r"((a)[2]), "r"((a)[3]), "r"(b0), "r"(b1))

__device__ __forceinline__ uint32_t pkf16(float lo, float hi) {
    uint32_t r;
    asm("cvt.rn.f16x2.f32 %0, %1, %2;" : "=r"(r) : "f"(hi), "f"(lo));
    return r;
}
__device__ __forceinline__ uint2 pack4(float4 v) {
    uint2 u;
    u.x = pkf16(v.x, v.y);
    u.y = pkf16(v.z, v.w);
    return u;
}

// ---------------- fp16 HMMA GEMM: C[M,N] = A[M,Kp] @ W[N,Kp]^T --------------
// CTA 128x128, 8 warps (2x4), warp 64x32, BK=64, 3-stage cp.async pipeline.
// EPI=0: fp16 store to C16.
// EPI=1: GLU epilogue -> fp16 HB over KP2.
// EPI=2: QKV epilogue: q/k RoPE (paired cols, fast trig) -> f16 head-major.
#define GSTAGES 3
#define GSTAGE_BYTES 32768          /* A 16KB + B 16KB */
#define GEMM_SMEM (GSTAGES * GSTAGE_BYTES)

template<int EPI>
__global__ void __launch_bounds__(256) gemm_mma_t(
    const __half* __restrict__ A, const __half* __restrict__ W,
    __half* __restrict__ C16, __half* __restrict__ HB,
    const float* __restrict__ gb, const float* __restrict__ lb,
    __half* __restrict__ Qd, __half* __restrict__ Kd, __half* __restrict__ Vd,
    int N, int Kp)
{
    extern __shared__ char sm[];
    const uint32_t smb = smem_u32(sm);
    const int tid  = threadIdx.x;
    const int wid  = tid >> 5, lane = tid & 31;
    const int wm   = (wid >> 2) << 6;
    const int wn   = (wid & 3) << 5;
    const int m0   = blockIdx.y << 7, n0 = blockIdx.x << 7;
    const int quad = lane >> 3, l8 = lane & 7;

    float acc[4][4][4];
#pragma unroll
    for (int i = 0; i < 4; ++i)
#pragma unroll
        for (int j = 0; j < 4; ++j)
#pragma unroll
            for (int v = 0; v < 4; ++v) acc[i][j][v] = 0.f;

    auto load_stage = [&](int kt) {
        const int s = kt % GSTAGES;
        const uint32_t sa = smb + s * GSTAGE_BYTES;
        const uint32_t sb = sa + 16384;
        const size_t kbase = (size_t)kt << 6;
#pragma unroll
        for (int p = 0; p < 4; ++p) {
            int chunk = (p << 8) + tid;
            int r = chunk >> 3, kc = chunk & 7;
            cpa16(sa + r * 128 + ((kc ^ (r & 7)) << 4),
                  (const char*)(A + (size_t)(m0 + r) * Kp + kbase + kc * 8));
        }
#pragma unroll
        for (int p = 0; p < 4; ++p) {
            int chunk = (p << 8) + tid;
            int r = chunk >> 3, kc = chunk & 7;
            cpa16(sb + r * 128 + ((kc ^ (r & 7)) << 4),
                  (const char*)(W + (size_t)(n0 + r) * Kp + kbase + kc * 8));
        }
        CP_COMMIT();
    };

    const int nk = Kp >> 6;
    load_stage(0);
    load_stage(1);

    for (int kt = 0; kt < nk; ++kt) {
        const int s = kt % GSTAGES;
        asm volatile("cp.async.wait_group 1;" ::: "memory");
        __syncthreads();
        if (kt + 2 < nk) load_stage(kt + 2); else CP_COMMIT();

        const uint32_t sa = smb + s * GSTAGE_BYTES;
        const uint32_t sb = sa + 16384;
#pragma unroll
        for (int ks = 0; ks < 4; ++ks) {
            const int k0c = ks << 1;
            uint32_t a[4][4], b[2][4];
#pragma unroll
            for (int mf = 0; mf < 4; ++mf) {
                int r  = wm + (mf << 4) + ((quad & 1) << 3) + l8;
                int kc = k0c + (quad >> 1);
                LDSM4(a[mf], sa + r * 128 + ((kc ^ (r & 7)) << 4));
            }
#pragma unroll
            for (int np = 0; np < 2; ++np) {
                int r  = wn + (np << 4) + ((quad >> 1) << 3) + l8;
                int kc = k0c + (quad & 1);
                LDSM4(b[np], sb + r * 128 + ((kc ^ (r & 7)) << 4));
            }
#pragma unroll
            for (int mf = 0; mf < 4; ++mf) {
#pragma unroll
                for (int np = 0; np < 2; ++np) {
                    MMAF16(acc[mf][2 * np],     a[mf], b[np][0], b[np][1]);
                    MMAF16(acc[mf][2 * np + 1], a[mf], b[np][2], b[np][3]);
                }
            }
        }
    }

    const int tr = lane >> 2, tc = (lane & 3) << 1;
    if (EPI == 0) {
#pragma unroll
        for (int mf = 0; mf < 4; ++mf) {
            int row = m0 + wm + (mf << 4) + tr;
            __half* c0 = C16 + (size_t)row * N + n0 + wn;
            __half* c1 = c0 + (size_t)8 * N;
#pragma unroll
            for (int nf = 0; nf < 4; ++nf) {
                __half2 v0 = {__float2half_rn(acc[mf][nf][0]),
                              __float2half_rn(acc[mf][nf][1])};
                __half2 v1 = {__float2half_rn(acc[mf][nf][2]),
                              __float2half_rn(acc[mf][nf][3])};
                *(__half2*)(c0 + (nf << 3) + tc) = v0;
                *(__half2*)(c1 + (nf << 3) + tc) = v1;
            }
        }
    } else if (EPI == 1) {
        // interleaved cols: even col = gate_c, odd col = lin_c, c = gcol>>1.
#pragma unroll
        for (int mf = 0; mf < 4; ++mf) {
            int row0 = m0 + wm + (mf << 4) + tr;
#pragma unroll
            for (int nf = 0; nf < 4; ++nf) {
                int c = (n0 + wn + (nf << 3) + tc) >> 1;
                float gbv = gb[c], lbv = lb[c];
                float h0 = (acc[mf][nf][1] + lbv) *
                           (1.f / (1.f + __expf(-(acc[mf][nf][0] + gbv))));
                float h1 = (acc[mf][nf][3] + lbv) *
                           (1.f / (1.f + __expf(-(acc[mf][nf][2] + gbv))));
                float h0p = __shfl_xor_sync(0xffffffffu, h0, 1);
                float h1p = __shfl_xor_sync(0xffffffffu, h1, 1);
                if ((lane & 1) == 0) {
                    __half2 hi0 = {__float2half_rn(h0), __float2half_rn(h0p)};
                    __half2 hi1 = {__float2half_rn(h1), __float2half_rn(h1p)};
                    __half* p0 = HB + (size_t)row0 * KP2 + c;
                    __half* p1 = p0 + (size_t)8 * KP2;
                    *(__half2*)(p0) = hi0;
                    *(__half2*)(p1) = hi1;
                }
            }
        }
    } else {
        // EPI == 2: QKV epilogue. Permuted weight rows -> thread holds RoPE
        // pair (x1_j, x2_j) in adjacent cols. q/k stored head-major f16.
        const float RC = 9.210340371976184f / 32.0f;
#pragma unroll
        for (int nf = 0; nf < 4; ++nf) {
            int col = n0 + wn + (nf << 3) + tc;   // even
            int sec = col >> 10;
            int cc  = col & 1023;
            int h   = cc >> 6, dd = cc & 63;
            if (sec < 2) {
                float invf = __expf(-(float)(dd >> 1) * RC);
                float scl = (sec == 0) ? 0.125f : 1.f;
                __half* dst = (sec == 0) ? Qd : Kd;
#pragma unroll
                for (int mf = 0; mf < 4; ++mf) {
                    int row = m0 + wm + (mf << 4) + tr;
#pragma unroll
                    for (int hf = 0; hf < 2; ++hf) {
                        int rr = row + (hf << 3);
                        int b = rr >> 11, sxx = rr & 2047;
                        float ph = (float)sxx * invf;
                        float co, si;
                        __sincosf(ph, &si, &co);
                        float x1 = acc[mf][nf][hf * 2], x2 = acc[mf][nf][hf * 2 + 1];
                        __half2 hp = {__float2half((x1 * co - x2 * si) * scl),
                                      __float2half((x1 * si + x2 * co) * scl)};
                        *(__half2*)(dst + (((size_t)(b * NH + h) * SS + sxx) << 6) + dd) = hp;
                    }
                }
            } else {
#pragma unroll
                for (int mf = 0; mf < 4; ++mf) {
                    int row = m0 + wm + (mf << 4) + tr;
#pragma unroll
                    for (int hf = 0; hf < 2; ++hf) {
                        int rr = row + (hf << 3);
                        int b = rr >> 11, sxx = rr & 2047;
                        __half2 hp = {__float2half(acc[mf][nf][hf * 2]),
                                      __float2half(acc[mf][nf][hf * 2 + 1])};
                        *(__half2*)(Vd + (((size_t)(b * NH + h) * SS + sxx) << 6) + dd) = hp;
                    }
                }
            }
        }
    }
}

// ---------------- merged fp32 -> fp16 conversions (one kernel, MLP=4) -------
#define CN0 (MTOT*DIMV/4)
#define CN1 (3*DIMV*DIMV/4)
#define CN2 (DIMV*DIMV/4)
#define CN3 (FFV*DIMV/4)
#define CN4 (DIMV*FFV/4)
#define CNT (CN0+CN1+CN2+CN3+CN4)
#define CITEMS 4
#define CTHREADS ((CNT + CITEMS - 1) / CITEMS)

__device__ __forceinline__ void conv_item(
    int idx,
    const float* __restrict__ x,      __half* __restrict__ xb,
    const float* __restrict__ qkvw,   __half* __restrict__ wqkv,
    const float* __restrict__ aow,    __half* __restrict__ wao,
    const float* __restrict__ gw, const float* __restrict__ lw,
    __half* __restrict__ wgl,
    const float* __restrict__ fow,    __half* __restrict__ wfo)
{
    if (idx < CN0) {
        *(uint2*)(xb + 4 * (size_t)idx) = pack4(*(const float4*)(x + 4 * (size_t)idx));
        return;
    }
    idx -= CN0;
    if (idx < CN1) {
        int row = idx >> 8, c4 = (idx & 255) << 2;
        int sec = row >> 10, within = row & 1023;
        int nrow = row;
        if (sec < 2) {
            int h = within >> 6, d = within & 63;
            nrow = (sec << 10) + (h << 6) + ((d & 31) << 1) + (d >> 5);
        }
        float4 v = *(const float4*)(qkvw + (size_t)row * DIMV + c4);
        *(uint2*)(wqkv + (size_t)nrow * KP1 + c4) = pack4(v);
        return;
    }
    idx -= CN1;
    if (idx < CN2) {
        *(uint2*)(wao + 4 * (size_t)idx) = pack4(*(const float4*)(aow + 4 * (size_t)idx));
        return;
    }
    idx -= CN2;
    if (idx < CN3) {
        int row = idx >> 8, c4 = (idx & 255) << 2;
        size_t src = (size_t)row * DIMV + c4;
        size_t bg  = (size_t)(2 * row) * KP1 + c4;
        *(uint2*)(wgl + bg)       = pack4(*(const float4*)(gw + src));
        *(uint2*)(wgl + bg + KP1) = pack4(*(const float4*)(lw + src));
        return;
    }
    idx -= CN3;
    if (idx < CN4) {
        *(uint2*)(wfo + 4 * (size_t)idx) = pack4(*(const float4*)(fow + 4 * (size_t)idx));
    }
}

__global__ void convert_all(
    const float* __restrict__ x,      __half* __restrict__ xb,
    const float* __restrict__ qkvw,   __half* __restrict__ wqkv,
    const float* __restrict__ aow,    __half* __restrict__ wao,
    const float* __restrict__ gw, const float* __restrict__ lw,
    __half* __restrict__ wgl,
    const float* __restrict__ fow,    __half* __restrict__ wfo)
{
    int base = blockIdx.x * blockDim.x + threadIdx.x;
#pragma unroll
    for (int it = 0; it < CITEMS; ++it) {
        int idx = base + it * CTHREADS;
        if (idx < CNT)
            conv_item(idx, x, xb, qkvw, wqkv, aow, wao, gw, lw, wgl, fow, wfo);
    }
}

// ---------------- flash attention, f16 HMMA ---------------------------------
// CTA = 64 q-rows, 4 warps. K/V staged in 128-row tiles (double-buffered,
// dynamic smem 72KB -> 3 CTAs/SM). Softmax once per 128 cols; masked tail.
#define ATT_SMEM (8192 + 2 * 32768)

__global__ void __launch_bounds__(128) attn_mma(
    const __half* __restrict__ qs, const __half* __restrict__ ks,
    const __half* __restrict__ vs, __half* __restrict__ ctxb)
{
    extern __shared__ __align__(16) char sm[];
    const uint32_t Qs = smem_u32(sm);
    const uint32_t Ss = Qs + 8192;
    const int qt = gridDim.x - 1 - blockIdx.x;  // heavy tiles first
    const int h = blockIdx.y, b = blockIdx.z;
    const int q0 = qt << 6;
    const int tid = threadIdx.x, wid = tid >> 5, lane = tid & 31;
    const int quad = lane >> 3, l8 = lane & 7;
    const int tr = lane >> 2, tc = (lane & 3) << 1;
    const int wq0 = wid << 4;
    const size_t bh = (size_t)(b * NH + h);
    const __half* qrow = qs + (bh * SS + q0) * 64;
    const __half* krow = ks + bh * SS * 64;
    const __half* vrow = vs + bh * SS * 64;

    for (int c = tid; c < 512; c += 128) {
        int r = c >> 3, kc = c & 7;
        cpa16(Qs + r * 128 + ((kc ^ (r & 7)) << 4),
              (const char*)(qrow + (size_t)r * 64) + kc * 16);
    }
    CP_COMMIT();

    // k-tiles are 128 rows wide
    auto load_stage = [&](int kt) {
        uint32_t Kst = Ss + (kt & 1) * 32768, Vst = Kst + 16384;
        const __half* kr = krow + ((size_t)kt << 7) * 64;
        const __half* vr = vrow + ((size_t)kt << 7) * 64;
        for (int c = tid; c < 1024; c += 128) {
            int r = c >> 3, kc = c & 7;
            cpa16(Kst + r * 128 + ((kc ^ (r & 7)) << 4),
                  (const char*)(kr + (size_t)r * 64) + kc * 16);
        }
        for (int c = tid; c < 1024; c += 128) {
            int r = c >> 3, kc = c & 7;
            cpa16(Vst + r * 128 + ((kc ^ (r & 7)) << 4),
                  (const char*)(vr + (size_t)r * 64) + kc * 16);
        }
        CP_COMMIT();
    };

    float m0r = -1e30f, m1r = -1e30f, l0 = 0.f, l1 = 0.f;
    float oacc[8][4];
#pragma unroll
    for (int i = 0; i < 8; ++i)
#pragma unroll
        for (int j = 0; j < 4; ++j) oacc[i][j] = 0.f;

    const int nt = (qt >> 1) + 1;   // 128-row tiles covering [0, q0+64)
    load_stage(0);

    for (int kt = 0; kt < nt; ++kt) {
        if (kt + 1 < nt) {
            load_stage(kt + 1);
            asm volatile("cp.async.wait_group 1;" ::: "memory");
        } else {
            asm volatile("cp.async.wait_group 0;" ::: "memory");
        }
        __syncthreads();
        const uint32_t Kst = Ss + (kt & 1) * 32768, Vst = Kst + 16384;

        // S = Q @ K^T over 128 columns
        float sacc[16][4];
#pragma unroll
        for (int i = 0; i < 16; ++i)
#pragma unroll
            for (int j = 0; j < 4; ++j) sacc[i][j] = 0.f;
#pragma unroll
        for (int ksp = 0; ksp < 4; ++ksp) {
            uint32_t a[4];
            {
                int r = wq0 + ((quad & 1) << 3) + l8;
                int kc = 2 * ksp + (quad >> 1);
                LDSM4(a, Qs + r * 128 + ((kc ^ (r & 7)) << 4));
            }
#pragma unroll
            for (int np = 0; np < 8; ++np) {
                uint32_t bf[4];
                int r = (np << 4) + ((quad >> 1) << 3) + l8;
                int kc = 2 * ksp + (quad & 1);
                LDSM4(bf, Kst + r * 128 + ((kc ^ (r & 7)) << 4));
                MMAF16(sacc[2 * np],     a, bf[0], bf[1]);
                MMAF16(sacc[2 * np + 1], a, bf[2], bf[3]);
            }
        }

        // causal mask on the final tile (covers cols beyond q0+63 too)
        if (kt == nt - 1) {
            int cbase = kt << 7;
            int r0 = q0 + wq0 + tr, r1 = r0 + 8;
#pragma unroll
            for (int nf = 0; nf < 16; ++nf) {
                int c0 = cbase + (nf << 3) + tc;
                if (c0     > r0) sacc[nf][0] = -1e30f;
                if (c0 + 1 > r0) sacc[nf][1] = -1e30f;
                if (c0     > r1) sacc[nf][2] = -1e30f;
                if (c0 + 1 > r1) sacc[nf][3] = -1e30f;
            }
        }

        float mx0 = -1e30f, mx1 = -1e30f;
#pragma unroll
        for (int nf = 0; nf < 16; ++nf) {
            mx0 = fmaxf(mx0, fmaxf(sacc[nf][0], sacc[nf][1]));
            mx1 = fmaxf(mx1, fmaxf(sacc[nf][2], sacc[nf][3]));
        }
        mx0 = fmaxf(mx0, __shfl_xor_sync(0xffffffffu, mx0, 1));
        mx0 = fmaxf(mx0, __shfl_xor_sync(0xffffffffu, mx0, 2));
        mx1 = fmaxf(mx1, __shfl_xor_sync(0xffffffffu, mx1, 1));
        mx1 = fmaxf(mx1, __shfl_xor_sync(0xffffffffu, mx1, 2));
        float mn0 = fmaxf(m0r, mx0), mn1 = fmaxf(m1r, mx1);
        float al0 = __expf(m0r - mn0), al1 = __expf(m1r - mn1);
        float rs0 = 0.f, rs1 = 0.f;
#pragma unroll
        for (int nf = 0; nf < 16; ++nf) {
            sacc[nf][0] = __expf(sacc[nf][0] - mn0);
            sacc[nf][1] = __expf(sacc[nf][1] - mn0);
            sacc[nf][2] = __expf(sacc[nf][2] - mn1);
            sacc[nf][3] = __expf(sacc[nf][3] - mn1);
            rs0 += sacc[nf][0] + sacc[nf][1];
            rs1 += sacc[nf][2] + sacc[nf][3];
        }
        rs0 += __shfl_xor_sync(0xffffffffu, rs0, 1);
        rs0 += __shfl_xor_sync(0xffffffffu, rs0, 2);
        rs1 += __shfl_xor_sync(0xffffffffu, rs1, 1);
        rs1 += __shfl_xor_sync(0xffffffffu, rs1, 2);
        l0 = l0 * al0 + rs0;
        l1 = l1 * al1 + rs1;
        m0r = mn0; m1r = mn1;
#pragma unroll
        for (int nf = 0; nf < 8; ++nf) {
            oacc[nf][0] *= al0; oacc[nf][1] *= al0;
            oacc[nf][2] *= al1; oacc[nf][3] *= al1;
        }

        // O += P @ V over 128 keys: 8 k-steps of 16
#pragma unroll
        for (int ksp = 0; ksp < 8; ++ksp) {
            uint32_t pa[4];
            pa[0] = pkf16(sacc[2 * ksp][0],     sacc[2 * ksp][1]);
            pa[1] = pkf16(sacc[2 * ksp][2],     sacc[2 * ksp][3]);
            pa[2] = pkf16(sacc[2 * ksp + 1][0], sacc[2 * ksp + 1][1]);
            pa[3] = pkf16(sacc[2 * ksp + 1][2], sacc[2 * ksp + 1][3]);
#pragma unroll
            for (int np = 0; np < 4; ++np) {
                uint32_t bf[4];
                int r  = (ksp << 4) + ((quad & 1) << 3) + l8;   // s rows 0..127
                int kc = 2 * np + (quad >> 1);                  // d chunk
                LDSM4T(bf, Vst + r * 128 + ((kc ^ (r & 7)) << 4));
                MMAF16(oacc[2 * np],     pa, bf[0], bf[1]);
                MMAF16(oacc[2 * np + 1], pa, bf[2], bf[3]);
            }
        }
        __syncthreads();
    }

    float i0 = 1.f / l0, i1 = 1.f / l1;
    int row0 = q0 + wq0 + tr;
    __half* p0 = ctxb + ((size_t)b * SS + row0) * KP1 + h * 64;
    __half* p1 = p0 + (size_t)8 * KP1;
#pragma unroll
    for (int nf = 0; nf < 8; ++nf) {
        int co = (nf << 3) + tc;
        __half2 hp0 = {__float2half_rn(oacc[nf][0] * i0),
                       __float2half_rn(oacc[nf][1] * i0)};
        __half2 hp1 = {__float2half_rn(oacc[nf][2] * i1),
                       __float2half_rn(oacc[nf][3] * i1)};
        *(__half2*)(p0 + co) = hp0;
        *(__half2*)(p1 + co) = hp1;
    }
}

// ---------------- norm: rms_norm(a + b) * scale -----------------------------
// AFP16=0: a fp32, emit fp16 OUTB only (x1 path).
// AFP16=1: a fp16, emit fp32 OUTF only (final output).
template<int AFP16>
__global__ __launch_bounds__(256) void addnorm_t(
    const void* __restrict__ aptr, const __half* __restrict__ bbuf,
    const float* __restrict__ scale, float* __restrict__ outf,
    __half* __restrict__ outb)
{
    const int row = blockIdx.x;
    const int tid = threadIdx.x;
    const size_t base = (size_t)row * DIMV;
    float4 av;
    if (AFP16) {
        uint2 a2 = *(const uint2*)((const __half*)aptr + base + 4 * tid);
        __half2 h0 = *(__half2*)&a2.x, h1 = *(__half2*)&a2.y;
        av = make_float4(__half2float(h0.x), __half2float(h0.y),
                         __half2float(h1.x), __half2float(h1.y));
    } else {
        av = *(const float4*)((const float*)aptr + base + 4 * tid);
    }
    uint2 b2 = *(const uint2*)(bbuf + base + 4 * tid);
    __half2 bh0 = *(__half2*)&b2.x, bh1 = *(__half2*)&b2.y;
    float4 v = make_float4(av.x + __half2float(bh0.x), av.y + __half2float(bh0.y),
                           av.z + __half2float(bh1.x), av.w + __half2float(bh1.y));
    float ss = fmaf(v.x, v.x, fmaf(v.y, v.y, fmaf(v.z, v.z, v.w * v.w)));
    __shared__ float red[8];
#pragma unroll
    for (int o = 16; o; o >>= 1) ss += __shfl_xor_sync(0xffffffffu, ss, o);
    if ((tid & 31) == 0) red[tid >> 5] = ss;
    __syncthreads();
    if (tid < 8) {
        float t = red[tid];
#pragma unroll
        for (int o = 4; o; o >>= 1) t += __shfl_xor_sync(0xffu, t, o);
        if (tid == 0) red[0] = t;
    }
    __syncthreads();
    float rms = sqrtf(red[0] * (1.f / 1024.f));
    float inv = 1.f / (rms + 1e-8f);
    float4 sc = *(const float4*)(scale + 4 * tid);
    float4 o4 = make_float4(sc.x * v.x * inv, sc.y * v.y * inv,
                            sc.z * v.z * inv, sc.w * v.w * inv);
    if (AFP16) *(float4*)(outf + base + 4 * tid) = o4;
    else       *(uint2*)(outb + base + 4 * tid) = pack4(o4);
}

// ---------------- launcher --------------------------------------------------
extern "C" void kernel_launch(void* const* d_in, const int* in_sizes, int n_in,
                              void* d_out, int out_size)
{
    (void)in_sizes; (void)n_in; (void)out_size;
    const float* x          = (const float*)d_in[0];
    const float* qkv_w      = (const float*)d_in[2];
    const float* attn_out_w = (const float*)d_in[3];
    const float* gate_w     = (const float*)d_in[4];
    const float* gate_b     = (const float*)d_in[5];
    const float* lin_w      = (const float*)d_in[6];
    const float* lin_b      = (const float*)d_in[7];
    const float* ff_out_w   = (const float*)d_in[8];
    const float* n1         = (const float*)d_in[9];
    const float* n2         = (const float*)d_in[10];
    float* out = (float*)d_out;

    __half *tmph, *qsb, *ksb, *vb;
    __half *xb, *ctxb, *x1b, *hb, *wqkv, *wao, *wgl, *wfo;
    cudaGetSymbolAddress((void**)&tmph, g_tmph);
    cudaGetSymbolAddress((void**)&qsb,  g_qs);
    cudaGetSymbolAddress((void**)&ksb,  g_ks);
    cudaGetSymbolAddress((void**)&vb,   g_v);
    cudaGetSymbolAddress((void**)&xb,   g_xb);
    cudaGetSymbolAddress((void**)&ctxb, g_ctxb);
    cudaGetSymbolAddress((void**)&x1b,  g_x1b);
    cudaGetSymbolAddress((void**)&hb,   g_hb);
    cudaGetSymbolAddress((void**)&wqkv, g_wqkv);
    cudaGetSymbolAddress((void**)&wao,  g_wao);
    cudaGetSymbolAddress((void**)&wgl,  g_wgl);
    cudaGetSymbolAddress((void**)&wfo,  g_wfo);

    cudaFuncSetAttribute(gemm_mma_t<0>, cudaFuncAttributeMaxDynamicSharedMemorySize, GEMM_SMEM);
    cudaFuncSetAttribute(gemm_mma_t<1>, cudaFuncAttributeMaxDynamicSharedMemorySize, GEMM_SMEM);
    cudaFuncSetAttribute(gemm_mma_t<2>, cudaFuncAttributeMaxDynamicSharedMemorySize, GEMM_SMEM);
    cudaFuncSetAttribute(attn_mma,      cudaFuncAttributeMaxDynamicSharedMemorySize, ATT_SMEM);

    // 0. all fp32 -> fp16 conversions in one kernel (MLP=4 per thread)
    convert_all<<<(CTHREADS + 255)/256, 256>>>(x, xb, qkv_w, wqkv, attn_out_w, wao,
                                               gate_w, lin_w, wgl, ff_out_w, wfo);

    // 1. QKV projection with fused RoPE epilogue -> q/k/v f16 head-major
    gemm_mma_t<2><<<dim3(3*DIMV/128, MTOT/128), 256, GEMM_SMEM>>>(
        xb, wqkv, nullptr, nullptr, nullptr, nullptr, qsb, ksb, vb, 3*DIMV, KP1);
    // 2. flash attention (64-q CTAs, 128-key tiles) -> fp16 ctx
    attn_mma<<<dim3(SS/64, NH, BB), 128, ATT_SMEM>>>(qsb, ksb, vb, ctxb);
    // 3. output projection -> fp16 tmph
    gemm_mma_t<0><<<dim3(DIMV/128, MTOT/128), 256, GEMM_SMEM>>>(
        ctxb, wao, tmph, nullptr, nullptr, nullptr, nullptr, nullptr, nullptr, DIMV, KP1);
    // 4. x1b = fp16 rmsnorm(x + tmph)
    addnorm_t<0><<<MTOT, 256>>>(x, tmph, n1, nullptr, x1b);
    // 5. fused gate+lin GEMM with GLU epilogue -> fp16 hb
    gemm_mma_t<1><<<dim3(2*FFV/128, MTOT/128), 256, GEMM_SMEM>>>(
        x1b, wgl, nullptr, hb, gate_b, lin_b, nullptr, nullptr, nullptr, 2*FFV, KP1);
    // 6. ff out -> fp16 tmph (reuse)
    gemm_mma_t<0><<<dim3(DIMV/128, MTOT/128), 256, GEMM_SMEM>>>(
        hb, wfo, tmph, nullptr, nullptr, nullptr, nullptr, nullptr, nullptr, DIMV, KP2);
    // 7. out = rmsnorm(x1b + tmph)  (fp32 output)
    addnorm_t<1><<<MTOT, 256>>>(x1b, tmph, n2, out, nullptr);
}